// round 3
// baseline (speedup 1.0000x reference)
#include <cuda_runtime.h>
#include <math.h>

#define B_ 1024
#define T_ 256
#define U_ 512
#define G4U (4 * U_)
#define P_ 32

#define BM 64      // batch tile per block
#define BU 64      // units tile per block (x4 gates)
#define KC 32      // K chunk
#define NTHREADS 256

// Persistent state (device globals = sanctioned scratch; no allocations).
__device__ float g_h[2][B_ * U_];   // ping-pong hidden state
__device__ float g_c[B_ * U_];      // cell state (updated in place)

// ---------------------------------------------------------------------------
// f32x2 packed-FMA helpers (Blackwell): 2 fp32 FMAs per instruction.
// ---------------------------------------------------------------------------
__device__ __forceinline__ unsigned long long pack2(float x) {
    unsigned long long r;
#if (defined(__CUDA_ARCH__) && __CUDA_ARCH__ >= 1000)
    asm("mov.b64 %0, {%1, %1};" : "=l"(r) : "f"(x));
#else
    union { unsigned long long u; float2 f; } t;
    t.f.x = x; t.f.y = x; r = t.u;
#endif
    return r;
}

__device__ __forceinline__ void fma2(unsigned long long& acc,
                                     unsigned long long a,
                                     unsigned long long b) {
#if (defined(__CUDA_ARCH__) && __CUDA_ARCH__ >= 1000)
    asm("fma.rn.f32x2 %0, %1, %2, %0;" : "+l"(acc) : "l"(a), "l"(b));
#else
    union { unsigned long long u; float2 f; } A, Bv, C;
    A.u = a; Bv.u = b; C.u = acc;
    C.f.x = fmaf(A.f.x, Bv.f.x, C.f.x);
    C.f.y = fmaf(A.f.y, Bv.f.y, C.f.y);
    acc = C.u;
#endif
}

__device__ __forceinline__ float sigmoidf_(float z) {
    return 1.0f / (1.0f + expf(-z));
}

// ---------------------------------------------------------------------------
// Zero initial state (h0 = c0 = 0) — must run each kernel_launch call so the
// whole launch is deterministic / graph-replayable.
// ---------------------------------------------------------------------------
__global__ void zero_state_kernel() {
    int i = blockIdx.x * blockDim.x + threadIdx.x;
    if (i < B_ * U_) {
        g_h[0][i] = 0.0f;
        g_c[i]    = 0.0f;
    }
}

// ---------------------------------------------------------------------------
// One LSTM time step, fused: Z = h@Wh (+ x*Wx + b), gates, c/h update.
//
// Block tile: BM=64 batch x BU=64 units (x 4 gates). Grid = (16, 8) = 128.
// 256 threads: warp -> 8 batch rows, lane -> units {lane, lane+32}.
// Accumulators are f32x2 pairs over (i,f) and (g,o) gates so the Wh operand
// loads from smem as a natural float2 with zero duplication; the h operand is
// warp-uniform (broadcast LDS, ~free) and lane-packed via mov.b64 on the ALU
// pipe, keeping the FMA pipe as the binding resource.
// ---------------------------------------------------------------------------
__global__ void __launch_bounds__(NTHREADS, 1)
lstm_step_kernel(const float* __restrict__ prices, int t,
                 const float* __restrict__ Wx,
                 const float* __restrict__ Wh,
                 const float* __restrict__ bias) {
    __shared__ float  Hs[KC][BM + 4];     // [k][b], +4 pad keeps rows 16B-aligned
    __shared__ float2 Wif[KC][BU];        // {W_i, W_f} per (k, u)
    __shared__ float2 Wgo[KC][BU];        // {W_g, W_o} per (k, u)

    const int tid  = threadIdx.x;
    const int lane = tid & 31;
    const int warp = tid >> 5;            // 0..7
    const int b0   = blockIdx.x * BM;
    const int u0   = blockIdx.y * BU;

    const float* __restrict__ h_in  = g_h[t & 1];
    float* __restrict__       h_out = g_h[(t + 1) & 1];

    unsigned long long acc_if[8][2];
    unsigned long long acc_go[8][2];
#pragma unroll
    for (int i = 0; i < 8; i++) {
        acc_if[i][0] = 0ull; acc_if[i][1] = 0ull;
        acc_go[i][0] = 0ull; acc_go[i][1] = 0ull;
    }

    const int bb = warp * 8;              // this warp's local batch base

    for (int kc = 0; kc < U_; kc += KC) {
        // ---- load H tile (transposed): Hs[k][b] = h_in[b0+b][kc+k] ----
        {
            int b_ld = tid >> 2;                  // 0..63
            int k_ld = (tid & 3) * 8;             // 0,8,16,24
            const float4* src = reinterpret_cast<const float4*>(
                &h_in[(b0 + b_ld) * U_ + kc + k_ld]);
            float4 v0 = src[0];
            float4 v1 = src[1];
            Hs[k_ld + 0][b_ld] = v0.x;
            Hs[k_ld + 1][b_ld] = v0.y;
            Hs[k_ld + 2][b_ld] = v0.z;
            Hs[k_ld + 3][b_ld] = v0.w;
            Hs[k_ld + 4][b_ld] = v1.x;
            Hs[k_ld + 5][b_ld] = v1.y;
            Hs[k_ld + 6][b_ld] = v1.z;
            Hs[k_ld + 7][b_ld] = v1.w;
        }
        // ---- load W tile: 32 k-rows x 4 gates x 64 u, gate-interleaved ----
#pragma unroll
        for (int i = 0; i < 8; i++) {
            int q  = tid + i * NTHREADS;          // quad index 0..2047
            int k  = q >> 6;                      // /64 quads per k-row
            int r  = q & 63;
            int g  = r >> 4;                      // gate 0..3
            int uq = (r & 15) * 4;                // u within tile (quad base)
            const float4 v = *reinterpret_cast<const float4*>(
                &Wh[(kc + k) * G4U + g * U_ + u0 + uq]);
            float vv[4] = {v.x, v.y, v.z, v.w};
            float* dstbase = (g < 2) ? &Wif[k][0].x : &Wgo[k][0].x;
            int half = g & 1;
#pragma unroll
            for (int l = 0; l < 4; l++)
                dstbase[2 * (uq + l) + half] = vv[l];
        }
        __syncthreads();

        // ---- FFMA2 mainloop ----
#pragma unroll 8
        for (int k = 0; k < KC; k++) {
            float4 h03 = *reinterpret_cast<const float4*>(&Hs[k][bb]);
            float4 h47 = *reinterpret_cast<const float4*>(&Hs[k][bb + 4]);
            unsigned long long wif0 =
                *reinterpret_cast<const unsigned long long*>(&Wif[k][lane]);
            unsigned long long wif1 =
                *reinterpret_cast<const unsigned long long*>(&Wif[k][lane + 32]);
            unsigned long long wgo0 =
                *reinterpret_cast<const unsigned long long*>(&Wgo[k][lane]);
            unsigned long long wgo1 =
                *reinterpret_cast<const unsigned long long*>(&Wgo[k][lane + 32]);
            float hv[8] = {h03.x, h03.y, h03.z, h03.w,
                           h47.x, h47.y, h47.z, h47.w};
#pragma unroll
            for (int i = 0; i < 8; i++) {
                unsigned long long hp = pack2(hv[i]);
                fma2(acc_if[i][0], hp, wif0);
                fma2(acc_if[i][1], hp, wif1);
                fma2(acc_go[i][0], hp, wgo0);
                fma2(acc_go[i][1], hp, wgo1);
            }
        }
        __syncthreads();
    }

    // ---- epilogue: add x*Wx + b, gates, update c and h ----
    float wxv[2][4], bv[2][4];
#pragma unroll
    for (int j = 0; j < 2; j++) {
        int u = u0 + lane + j * 32;
#pragma unroll
        for (int g = 0; g < 4; g++) {
            wxv[j][g] = Wx[g * U_ + u];
            bv[j][g]  = bias[g * U_ + u];
        }
    }
#pragma unroll
    for (int i = 0; i < 8; i++) {
        int b = b0 + bb + i;
        float x = prices[b * T_ + t];
#pragma unroll
        for (int j = 0; j < 2; j++) {
            int u = u0 + lane + j * 32;
            union { unsigned long long u64; float2 f; } cif, cgo;
            cif.u64 = acc_if[i][j];
            cgo.u64 = acc_go[i][j];
            float zi = fmaf(x, wxv[j][0], cif.f.x + bv[j][0]);
            float zf = fmaf(x, wxv[j][1], cif.f.y + bv[j][1]);
            float zg = fmaf(x, wxv[j][2], cgo.f.x + bv[j][2]);
            float zo = fmaf(x, wxv[j][3], cgo.f.y + bv[j][3]);
            float ig = sigmoidf_(zi);
            float fg = sigmoidf_(zf);
            float gg = tanhf(zg);
            float og = sigmoidf_(zo);
            int idx = b * U_ + u;
            float c = fmaf(fg, g_c[idx], ig * gg);
            g_c[idx]   = c;
            h_out[idx] = og * tanhf(c);
        }
    }
}

// ---------------------------------------------------------------------------
// Head: out = relu(h @ Wd + bd) @ Wp + bp.  h lives in g_h[0] after T=256
// steps ((255+1)&1 == 0). One block per batch row, 64 threads.
// ---------------------------------------------------------------------------
__global__ void head_kernel(const float* __restrict__ Wd,
                            const float* __restrict__ bd,
                            const float* __restrict__ Wp,
                            const float* __restrict__ bp,
                            float* __restrict__ out) {
    __shared__ float xs[64];
    int b = blockIdx.x;
    int j = threadIdx.x;                      // 0..63
    const float* hr = &g_h[0][b * U_];
    float s = bd[j];
#pragma unroll 8
    for (int k = 0; k < U_; k++)
        s = fmaf(hr[k], Wd[k * 64 + j], s);   // hr[k] is warp-uniform
    xs[j] = fmaxf(s, 0.0f);
    __syncthreads();
    if (j < P_) {
        float s2 = bp[j];
#pragma unroll
        for (int k = 0; k < 64; k++)
            s2 = fmaf(xs[k], Wp[k * P_ + j], s2);
        out[b * P_ + j] = s2;
    }
}

// ---------------------------------------------------------------------------
// kernel_launch: zero state, 256 sequential step kernels (graph nodes), head.
// All launches on the default stream -> graph-capturable, no allocations, no
// syncs, deterministic.
// ---------------------------------------------------------------------------
extern "C" void kernel_launch(void* const* d_in, const int* in_sizes, int n_in,
                              void* d_out, int out_size) {
    const float* prices = (const float*)d_in[0];  // [B, T]
    const float* Wx     = (const float*)d_in[1];  // [1, 4U]
    const float* Wh     = (const float*)d_in[2];  // [U, 4U]
    const float* bias   = (const float*)d_in[3];  // [4U]
    const float* Wd     = (const float*)d_in[4];  // [U, 64]
    const float* bd     = (const float*)d_in[5];  // [64]
    const float* Wp     = (const float*)d_in[6];  // [64, P]
    const float* bp     = (const float*)d_in[7];  // [P]
    float* out          = (float*)d_out;          // [B, P]

    (void)in_sizes; (void)n_in; (void)out_size;

    zero_state_kernel<<<(B_ * U_ + 255) / 256, 256>>>();

    dim3 grid(B_ / BM, U_ / BU);                  // (16, 8) = 128 blocks
    for (int t = 0; t < T_; t++) {
        lstm_step_kernel<<<grid, NTHREADS>>>(prices, t, Wx, Wh, bias);
    }

    head_kernel<<<B_, 64>>>(Wd, bd, Wp, bp, out);
}

// round 4
// speedup vs baseline: 1.1800x; 1.1800x over previous
#include <cuda_runtime.h>
#include <math.h>

#define B_ 1024
#define T_ 256
#define U_ 512
#define G4U (4 * U_)
#define P_ 32

#define BM 64      // batch tile per block
#define BU 32      // units tile per block (x4 gates)
#define KC 32      // K chunk
#define NTHREADS 256
#define NUT (U_ / BU)   // 16 u-tiles

// Persistent scratch (device globals = sanctioned; no allocations).
// h is stored TRANSPOSED: g_h[buf][u * B_ + b]  -> step-kernel H-tile loads
// are straight coalesced copies (no scatter).
__device__ float  g_h[2][U_ * B_];
__device__ float  g_c[B_ * U_];              // cell state, [b][u] layout
// Pre-interleaved Wh: [ut][k][64] float2 ; slots 0..31 = {Wi,Wf}(u), 32..63 = {Wg,Wo}(u)
__device__ float2 g_Whp[NUT * U_ * 64];

typedef unsigned long long ull;

// ---------------------------------------------------------------------------
// f32x2 packed-FMA helpers (Blackwell): 2 fp32 FMAs per instruction.
// ---------------------------------------------------------------------------
__device__ __forceinline__ ull pack2(float x) {
    ull r;
    asm("mov.b64 %0, {%1, %1};" : "=l"(r) : "f"(x));
    return r;
}
__device__ __forceinline__ void fma2(ull& acc, ull a, ull b) {
    asm("fma.rn.f32x2 %0, %1, %2, %0;" : "+l"(acc) : "l"(a), "l"(b));
}
__device__ __forceinline__ float fast_tanh(float x) {
    float y;
    asm("tanh.approx.f32 %0, %1;" : "=f"(y) : "f"(x));
    return y;
}
__device__ __forceinline__ float fast_sigmoid(float z) {
    // sigmoid(z) = 0.5 * tanh(z/2) + 0.5  (single MUFU-class op)
    return fmaf(0.5f, fast_tanh(0.5f * z), 0.5f);
}

// ---------------------------------------------------------------------------
// Zero initial state.
// ---------------------------------------------------------------------------
__global__ void zero_state_kernel() {
    int i = blockIdx.x * blockDim.x + threadIdx.x;
    if (i < B_ * U_) {
        g_h[0][i] = 0.0f;
        g_c[i]    = 0.0f;
    }
}

// ---------------------------------------------------------------------------
// One-shot Wh re-layout: gate-interleaved float2 pairs, chunk-contiguous, so
// the step kernel's W-tile load is a pure coalesced float4 copy.
// ---------------------------------------------------------------------------
__global__ void prep_w_kernel(const float* __restrict__ Wh) {
    int idx = blockIdx.x * blockDim.x + threadIdx.x;   // < 16*512*64
    if (idx >= NUT * U_ * 64) return;
    int slot = idx & 63;
    int k    = (idx >> 6) & (U_ - 1);
    int ut   = idx >> 15;
    int half = slot >> 5;           // 0: {i,f}  1: {g,o}
    int j    = slot & 31;
    int u    = ut * BU + j;
    float2 v;
    v.x = Wh[k * G4U + (half * 2 + 0) * U_ + u];
    v.y = Wh[k * G4U + (half * 2 + 1) * U_ + u];
    g_Whp[idx] = v;
}

// ---------------------------------------------------------------------------
// One LSTM step. Grid (16,16)=256 blocks, 256 threads, 2 blocks/SM.
// warp -> 8 batch rows, lane -> unit u0+lane. Accumulators are f32x2 over
// gate pairs (i,f)/(g,o); W loads as natural float2 from smem; h is a
// warp-uniform broadcast packed via mov.b64 on the ALU pipe.
// ---------------------------------------------------------------------------
__global__ void __launch_bounds__(NTHREADS, 2)
lstm_step_kernel(const float* __restrict__ prices, int t,
                 const float* __restrict__ Wx,
                 const float* __restrict__ bias) {
    __shared__ float                Hs[KC][BM];     // [k][b]
    __shared__ __align__(16) float2 W2[KC][64];     // [k][slot]

    const int tid  = threadIdx.x;
    const int lane = tid & 31;
    const int warp = tid >> 5;              // 0..7
    const int b0   = blockIdx.x * BM;
    const int ut   = blockIdx.y;
    const int u0   = ut * BU;
    const int bb   = warp * 8;

    const float* __restrict__ h_in  = g_h[t & 1];
    float* __restrict__       h_out = g_h[(t + 1) & 1];

    ull acc_if[8], acc_go[8];
#pragma unroll
    for (int i = 0; i < 8; i++) { acc_if[i] = 0ull; acc_go[i] = 0ull; }

    for (int kc = 0; kc < U_; kc += KC) {
        // H tile: straight coalesced copy (h is transposed in gmem)
#pragma unroll
        for (int i = 0; i < 2; i++) {
            int q  = tid + i * NTHREADS;        // 0..511 float4 units
            int k  = q >> 4;
            int b4 = (q & 15) << 2;
            *reinterpret_cast<float4*>(&Hs[k][b4]) =
                *reinterpret_cast<const float4*>(&h_in[(kc + k) * B_ + b0 + b4]);
        }
        // W tile: contiguous 16KB copy from pre-interleaved layout
        {
            const float4* wsrc = reinterpret_cast<const float4*>(
                g_Whp + ((size_t)ut * U_ + kc) * 64);
            float4* wdst = reinterpret_cast<float4*>(&W2[0][0]);
#pragma unroll
            for (int i = 0; i < 4; i++)
                wdst[tid + i * NTHREADS] = wsrc[tid + i * NTHREADS];
        }
        __syncthreads();

#pragma unroll 8
        for (int k = 0; k < KC; k++) {
            float4 h03 = *reinterpret_cast<const float4*>(&Hs[k][bb]);
            float4 h47 = *reinterpret_cast<const float4*>(&Hs[k][bb + 4]);
            ull wif = *reinterpret_cast<const ull*>(&W2[k][lane]);
            ull wgo = *reinterpret_cast<const ull*>(&W2[k][32 + lane]);
            float hv[8] = {h03.x, h03.y, h03.z, h03.w,
                           h47.x, h47.y, h47.z, h47.w};
#pragma unroll
            for (int i = 0; i < 8; i++) {
                ull hp = pack2(hv[i]);
                fma2(acc_if[i], hp, wif);
                fma2(acc_go[i], hp, wgo);
            }
        }
        __syncthreads();
    }

    // ---- epilogue: gates, c update, h (with smem transpose for coalesced
    //      transposed h_out writes) ----
    const int u = u0 + lane;
    const float wx0 = Wx[0 * U_ + u], wx1 = Wx[1 * U_ + u];
    const float wx2 = Wx[2 * U_ + u], wx3 = Wx[3 * U_ + u];
    const float bv0 = bias[0 * U_ + u], bv1 = bias[1 * U_ + u];
    const float bv2 = bias[2 * U_ + u], bv3 = bias[3 * U_ + u];

    float hval[8];
#pragma unroll
    for (int i = 0; i < 8; i++) {
        int b = b0 + bb + i;
        float x = prices[b * T_ + t];
        union { ull u64; float2 f; } cif, cgo;
        cif.u64 = acc_if[i];
        cgo.u64 = acc_go[i];
        float zi = fmaf(x, wx0, cif.f.x + bv0);
        float zf = fmaf(x, wx1, cif.f.y + bv1);
        float zg = fmaf(x, wx2, cgo.f.x + bv2);
        float zo = fmaf(x, wx3, cgo.f.y + bv3);
        float ig = fast_sigmoid(zi);
        float fg = fast_sigmoid(zf);
        float gg = fast_tanh(zg);
        float og = fast_sigmoid(zo);
        int cidx = b * U_ + u;                   // coalesced over lanes
        float c = fmaf(fg, g_c[cidx], ig * gg);
        g_c[cidx] = c;
        hval[i] = og * fast_tanh(c);
    }

    // transpose 64b x 32u through smem (stride 65 -> conflict-free STS)
    float* Tt = reinterpret_cast<float*>(&W2[0][0]);   // needs 32*65 floats
#pragma unroll
    for (int i = 0; i < 8; i++)
        Tt[lane * 65 + bb + i] = hval[i];
    __syncthreads();
    {
        int up = tid >> 3;                 // 0..31
        int bp = (tid & 7) * 8;            // 0..56
        float4 v0, v1;
        v0.x = Tt[up * 65 + bp + 0]; v0.y = Tt[up * 65 + bp + 1];
        v0.z = Tt[up * 65 + bp + 2]; v0.w = Tt[up * 65 + bp + 3];
        v1.x = Tt[up * 65 + bp + 4]; v1.y = Tt[up * 65 + bp + 5];
        v1.z = Tt[up * 65 + bp + 6]; v1.w = Tt[up * 65 + bp + 7];
        float* dst = &h_out[(u0 + up) * B_ + b0 + bp];
        *reinterpret_cast<float4*>(dst)     = v0;
        *reinterpret_cast<float4*>(dst + 4) = v1;
    }
}

// ---------------------------------------------------------------------------
// Head: out = relu(h @ Wd + bd) @ Wp + bp.  Final h is in g_h[0], transposed.
// ---------------------------------------------------------------------------
__global__ void head_kernel(const float* __restrict__ Wd,
                            const float* __restrict__ bd,
                            const float* __restrict__ Wp,
                            const float* __restrict__ bp,
                            float* __restrict__ out) {
    __shared__ float xs[64];
    int b = blockIdx.x;
    int j = threadIdx.x;                      // 0..63
    float s = bd[j];
#pragma unroll 8
    for (int k = 0; k < U_; k++)
        s = fmaf(g_h[0][k * B_ + b], Wd[k * 64 + j], s);  // h warp-uniform
    xs[j] = fmaxf(s, 0.0f);
    __syncthreads();
    if (j < P_) {
        float s2 = bp[j];
#pragma unroll
        for (int k = 0; k < 64; k++)
            s2 = fmaf(xs[k], Wp[k * P_ + j], s2);
        out[b * P_ + j] = s2;
    }
}

// ---------------------------------------------------------------------------
// kernel_launch: zero + prep, 256 step kernels, head. Graph-capturable.
// ---------------------------------------------------------------------------
extern "C" void kernel_launch(void* const* d_in, const int* in_sizes, int n_in,
                              void* d_out, int out_size) {
    const float* prices = (const float*)d_in[0];  // [B, T]
    const float* Wx     = (const float*)d_in[1];  // [1, 4U]
    const float* Wh     = (const float*)d_in[2];  // [U, 4U]
    const float* bias   = (const float*)d_in[3];  // [4U]
    const float* Wd     = (const float*)d_in[4];  // [U, 64]
    const float* bd     = (const float*)d_in[5];  // [64]
    const float* Wp     = (const float*)d_in[6];  // [64, P]
    const float* bp     = (const float*)d_in[7];  // [P]
    float* out          = (float*)d_out;          // [B, P]

    (void)in_sizes; (void)n_in; (void)out_size;

    zero_state_kernel<<<(B_ * U_ + 255) / 256, 256>>>();
    prep_w_kernel<<<(NUT * U_ * 64 + 255) / 256, 256>>>(Wh);

    dim3 grid(B_ / BM, NUT);                      // (16, 16) = 256 blocks
    for (int t = 0; t < T_; t++) {
        lstm_step_kernel<<<grid, NTHREADS>>>(prices, t, Wx, bias);
    }

    head_kernel<<<B_, 64>>>(Wd, bd, Wp, bp, out);
}